// round 13
// baseline (speedup 1.0000x reference)
#include <cuda_runtime.h>
#include <cuda_fp16.h>
#include <mma.h>
#include <math.h>

using namespace nvcuda;

#define N_NODES 100000
#define N_EDGES 1000000
#define D 64
#define CAP 64                       // bucket capacity; P(Poisson(10) > 64) ~ 1e-30

// Scratch (allocation-free contract: __device__ globals)
__device__ __half g_xwh[N_NODES * D];   // GEMM output, fp16 (both layers)
__device__ __half g_hh[N_NODES * D];    // h1, fp16 (GEMM2 input)
__device__ float  g_dinv[N_NODES];      // (deg+1)^-1/2
__device__ int    g_count[N_NODES];     // in-degree (atomic fill counters)
__device__ int    g_slot[N_NODES * CAP];// bucket: src nodes per dst
__device__ float  g_na[N_NODES];        // h2 . w_lin[0:64]
__device__ float  g_nb[N_NODES];        // h2 . w_lin[64:128]

__device__ __forceinline__ int clampi(int v) {
    return v < 0 ? 0 : (v >= N_NODES ? N_NODES - 1 : v);
}

__device__ __forceinline__ unsigned long long pack2(float a, float b) {
    unsigned long long r;
    asm("mov.b64 %0, {%1, %2};" : "=l"(r) : "f"(a), "f"(b));
    return r;
}
__device__ __forceinline__ void unpack2(unsigned long long v, float& a, float& b) {
    asm("mov.b64 {%0, %1}, %2;" : "=f"(a), "=f"(b) : "l"(v));
}
__device__ __forceinline__ void ffma2(unsigned long long& d, unsigned long long a,
                                      unsigned long long b) {
    asm("fma.rn.f32x2 %0, %1, %2, %0;" : "+l"(d) : "l"(a), "l"(b));
}

// accumulate 8 halves (one uint4) scaled by s into acc[8]
__device__ __forceinline__ void acc_halves(float* acc, uint4 v, float s) {
    __half2 h0 = *reinterpret_cast<__half2*>(&v.x);
    __half2 h1 = *reinterpret_cast<__half2*>(&v.y);
    __half2 h2 = *reinterpret_cast<__half2*>(&v.z);
    __half2 h3 = *reinterpret_cast<__half2*>(&v.w);
    float2 f0 = __half22float2(h0);
    float2 f1 = __half22float2(h1);
    float2 f2 = __half22float2(h2);
    float2 f3 = __half22float2(h3);
    acc[0] = fmaf(f0.x, s, acc[0]); acc[1] = fmaf(f0.y, s, acc[1]);
    acc[2] = fmaf(f1.x, s, acc[2]); acc[3] = fmaf(f1.y, s, acc[3]);
    acc[4] = fmaf(f2.x, s, acc[4]); acc[5] = fmaf(f2.y, s, acc[5]);
    acc[6] = fmaf(f3.x, s, acc[6]); acc[7] = fmaf(f3.y, s, acc[7]);
}

// ---------------------------------------------------------------------------
// single-pass bucket fill: slot[c*CAP + pos] = r
// ---------------------------------------------------------------------------
__global__ void __launch_bounds__(256) fill_buckets(const int* __restrict__ row,
                                                    const int* __restrict__ col) {
    int e = blockIdx.x * blockDim.x + threadIdx.x;
    if (e >= N_EDGES) return;
    int r = clampi(row[e]);
    int c = clampi(col[e]);
    int pos = atomicAdd(&g_count[c], 1);
    if (pos < CAP) g_slot[c * CAP + pos] = r;
}

__global__ void __launch_bounds__(256) make_dinv() {
    int i = blockIdx.x * blockDim.x + threadIdx.x;
    if (i < N_NODES) g_dinv[i] = rsqrtf((float)(g_count[i] + 1));
}

// ---------------------------------------------------------------------------
// layer-1 GEMM (packed f32x2 FMA), fp32 input, fp16 output: C = A @ W
// ---------------------------------------------------------------------------
__global__ void __launch_bounds__(256) gemm64_f32(const float* __restrict__ A,
                                                  const float* __restrict__ W,
                                                  __half* __restrict__ C, int n) {
    __shared__ ulonglong2 ws[1024];  // W as [64][16] float4 -> packed pairs
    const float4* W4 = (const float4*)W;
    for (int i = threadIdx.x; i < 1024; i += 256) {
        float4 w = W4[i];
        ulonglong2 u;
        u.x = pack2(w.x, w.y);
        u.y = pack2(w.z, w.w);
        ws[i] = u;
    }
    __syncthreads();

    int g  = threadIdx.x >> 4;
    int j4 = threadIdx.x & 15;
    int r0 = blockIdx.x * 64 + g * 4;

    ulonglong2 acc[4];
    #pragma unroll
    for (int i = 0; i < 4; i++) { acc[i].x = 0ull; acc[i].y = 0ull; }

    const float4* a[4];
    bool valid[4];
    #pragma unroll
    for (int i = 0; i < 4; i++) {
        int r = r0 + i;
        valid[i] = (r < n);
        a[i] = (const float4*)(A + (size_t)(valid[i] ? r : 0) * D);
    }

    #pragma unroll 4
    for (int kk = 0; kk < 16; kk++) {
        float4 xv[4];
        #pragma unroll
        for (int i = 0; i < 4; i++) xv[i] = __ldg(&a[i][kk]);
        #pragma unroll
        for (int s = 0; s < 4; s++) {
            ulonglong2 w = ws[(kk * 4 + s) * 16 + j4];
            #pragma unroll
            for (int i = 0; i < 4; i++) {
                float xs = (s == 0) ? xv[i].x : (s == 1) ? xv[i].y
                         : (s == 2) ? xv[i].z : xv[i].w;
                unsigned long long xs2 = pack2(xs, xs);
                ffma2(acc[i].x, xs2, w.x);
                ffma2(acc[i].y, xs2, w.y);
            }
        }
    }

    #pragma unroll
    for (int i = 0; i < 4; i++) {
        if (valid[i]) {
            float4 o;
            unpack2(acc[i].x, o.x, o.y);
            unpack2(acc[i].y, o.z, o.w);
            __half2 p0 = __floats2half2_rn(o.x, o.y);
            __half2 p1 = __floats2half2_rn(o.z, o.w);
            uint2 st;
            st.x = *reinterpret_cast<unsigned*>(&p0);
            st.y = *reinterpret_cast<unsigned*>(&p1);
            ((uint2*)(C + (size_t)(r0 + i) * D))[j4] = st;
        }
    }
}

// ---------------------------------------------------------------------------
// layer-2 GEMM via tensor cores (wmma m16n16k16, fp16 in, fp32 accum):
//   C[n,:] = ((A[n,:] @ W) * dinv[n]) as fp16
// 256 threads = 8 warps; 128 rows per block, 16 rows per warp, N=64.
// ---------------------------------------------------------------------------
__global__ void __launch_bounds__(256) gemm64_wmma(const __half* __restrict__ A,
                                                   const float* __restrict__ W,
                                                   __half* __restrict__ C, int n) {
    __shared__ __half wsh[64 * 64];          // 8 KB, W in fp16 row-major [K][N]
    __shared__ float  ctile[8 * 16 * 64];    // 32 KB, per-warp epilogue staging

    for (int i = threadIdx.x; i < 64 * 64; i += 256)
        wsh[i] = __float2half_rn(W[i]);
    __syncthreads();

    int warp = threadIdx.x >> 5;
    int lane = threadIdx.x & 31;
    int row0 = blockIdx.x * 128 + warp * 16;
    if (row0 >= n) return;   // n % 16 == 0, so a live warp always has 16 full rows

    wmma::fragment<wmma::accumulator, 16, 16, 16, float> c_frag[4];
    #pragma unroll
    for (int j = 0; j < 4; j++) wmma::fill_fragment(c_frag[j], 0.0f);

    #pragma unroll
    for (int k = 0; k < 4; k++) {
        wmma::fragment<wmma::matrix_a, 16, 16, 16, __half, wmma::row_major> a_frag;
        wmma::load_matrix_sync(a_frag, A + (size_t)row0 * D + k * 16, D);
        #pragma unroll
        for (int j = 0; j < 4; j++) {
            wmma::fragment<wmma::matrix_b, 16, 16, 16, __half, wmma::row_major> b_frag;
            wmma::load_matrix_sync(b_frag, wsh + k * 16 * 64 + j * 16, 64);
            wmma::mma_sync(c_frag[j], a_frag, b_frag, c_frag[j]);
        }
    }

    float* ct = ctile + warp * 16 * 64;
    #pragma unroll
    for (int j = 0; j < 4; j++)
        wmma::store_matrix_sync(ct + j * 16, c_frag[j], 64, wmma::mem_row_major);
    __syncwarp();

    // epilogue: 2 lanes per row; scale by dinv, convert, 16B stores
    int r = lane >> 1;
    int half = lane & 1;
    int gr = row0 + r;
    float sc = g_dinv[gr];
    const float* src = ct + r * 64 + half * 32;
    __half* dst = C + (size_t)gr * D + half * 32;
    #pragma unroll
    for (int it = 0; it < 4; it++) {
        float4 fa = *(const float4*)(src + it * 8);
        float4 fb = *(const float4*)(src + it * 8 + 4);
        __half2 p0 = __floats2half2_rn(fa.x * sc, fa.y * sc);
        __half2 p1 = __floats2half2_rn(fa.z * sc, fa.w * sc);
        __half2 p2 = __floats2half2_rn(fb.x * sc, fb.y * sc);
        __half2 p3 = __floats2half2_rn(fb.z * sc, fb.w * sc);
        uint4 st;
        st.x = *reinterpret_cast<unsigned*>(&p0);
        st.y = *reinterpret_cast<unsigned*>(&p1);
        st.z = *reinterpret_cast<unsigned*>(&p2);
        st.w = *reinterpret_cast<unsigned*>(&p3);
        *(uint4*)(dst + it * 8) = st;
    }
}

// ---------------------------------------------------------------------------
// layer-1 aggregate (apply dinv[src] per edge), fp16 in/out:
//   h[n] = relu(dinv[n]*(xw[n]*dinv[n] + sum xw[src]*dinv[src]) + b)
// 8 threads per node (one uint4 = 8 halves each), unrolled x4.
// ---------------------------------------------------------------------------
__global__ void __launch_bounds__(256) aggregate1(const float* __restrict__ bias) {
    int node = blockIdx.x * 32 + (threadIdx.x >> 3);
    int f8 = threadIdx.x & 7;
    if (node >= N_NODES) return;
    const uint4* xw8 = (const uint4*)g_xwh;

    float di = g_dinv[node];
    float acc[8] = {0, 0, 0, 0, 0, 0, 0, 0};
    acc_halves(acc, __ldg(&xw8[(size_t)node * 8 + f8]), di);

    const int* slots = g_slot + (size_t)node * CAP;
    int cnt = g_count[node];
    if (cnt > CAP) cnt = CAP;
    int i = 0;
    for (; i + 3 < cnt; i += 4) {
        int s0 = __ldg(&slots[i]);
        int s1 = __ldg(&slots[i + 1]);
        int s2 = __ldg(&slots[i + 2]);
        int s3 = __ldg(&slots[i + 3]);
        float d0 = __ldg(&g_dinv[s0]);
        float d1 = __ldg(&g_dinv[s1]);
        float d2 = __ldg(&g_dinv[s2]);
        float d3 = __ldg(&g_dinv[s3]);
        uint4 v0 = __ldg(&xw8[(size_t)s0 * 8 + f8]);
        uint4 v1 = __ldg(&xw8[(size_t)s1 * 8 + f8]);
        uint4 v2 = __ldg(&xw8[(size_t)s2 * 8 + f8]);
        uint4 v3 = __ldg(&xw8[(size_t)s3 * 8 + f8]);
        acc_halves(acc, v0, d0);
        acc_halves(acc, v1, d1);
        acc_halves(acc, v2, d2);
        acc_halves(acc, v3, d3);
    }
    for (; i < cnt; i++) {
        int s0 = __ldg(&slots[i]);
        float d0 = __ldg(&g_dinv[s0]);
        acc_halves(acc, __ldg(&xw8[(size_t)s0 * 8 + f8]), d0);
    }

    const float4* b4 = (const float4*)bias;
    float4 ba = __ldg(&b4[f8 * 2]);
    float4 bb = __ldg(&b4[f8 * 2 + 1]);
    float o[8];
    o[0] = fmaxf(fmaf(di, acc[0], ba.x), 0.f);
    o[1] = fmaxf(fmaf(di, acc[1], ba.y), 0.f);
    o[2] = fmaxf(fmaf(di, acc[2], ba.z), 0.f);
    o[3] = fmaxf(fmaf(di, acc[3], ba.w), 0.f);
    o[4] = fmaxf(fmaf(di, acc[4], bb.x), 0.f);
    o[5] = fmaxf(fmaf(di, acc[5], bb.y), 0.f);
    o[6] = fmaxf(fmaf(di, acc[6], bb.z), 0.f);
    o[7] = fmaxf(fmaf(di, acc[7], bb.w), 0.f);
    __half2 p0 = __floats2half2_rn(o[0], o[1]);
    __half2 p1 = __floats2half2_rn(o[2], o[3]);
    __half2 p2 = __floats2half2_rn(o[4], o[5]);
    __half2 p3 = __floats2half2_rn(o[6], o[7]);
    uint4 st;
    st.x = *reinterpret_cast<unsigned*>(&p0);
    st.y = *reinterpret_cast<unsigned*>(&p1);
    st.z = *reinterpret_cast<unsigned*>(&p2);
    st.w = *reinterpret_cast<unsigned*>(&p3);
    ((uint4*)g_hh)[(size_t)node * 8 + f8] = st;
}

// ---------------------------------------------------------------------------
// layer-2 aggregate (GEMM2 dinv-folded -> pure sum), fused edge head
// ---------------------------------------------------------------------------
__global__ void __launch_bounds__(256) aggregate2(const float* __restrict__ bias,
                                                  const float* __restrict__ wl) {
    int node = blockIdx.x * 32 + (threadIdx.x >> 3);
    int f8 = threadIdx.x & 7;
    if (node >= N_NODES) return;
    const uint4* xw8 = (const uint4*)g_xwh;

    float acc[8] = {0, 0, 0, 0, 0, 0, 0, 0};
    acc_halves(acc, __ldg(&xw8[(size_t)node * 8 + f8]), 1.0f);

    const int* slots = g_slot + (size_t)node * CAP;
    int cnt = g_count[node];
    if (cnt > CAP) cnt = CAP;
    int i = 0;
    for (; i + 3 < cnt; i += 4) {
        int s0 = __ldg(&slots[i]);
        int s1 = __ldg(&slots[i + 1]);
        int s2 = __ldg(&slots[i + 2]);
        int s3 = __ldg(&slots[i + 3]);
        uint4 v0 = __ldg(&xw8[(size_t)s0 * 8 + f8]);
        uint4 v1 = __ldg(&xw8[(size_t)s1 * 8 + f8]);
        uint4 v2 = __ldg(&xw8[(size_t)s2 * 8 + f8]);
        uint4 v3 = __ldg(&xw8[(size_t)s3 * 8 + f8]);
        acc_halves(acc, v0, 1.0f);
        acc_halves(acc, v1, 1.0f);
        acc_halves(acc, v2, 1.0f);
        acc_halves(acc, v3, 1.0f);
    }
    for (; i < cnt; i++) {
        int s0 = __ldg(&slots[i]);
        acc_halves(acc, __ldg(&xw8[(size_t)s0 * 8 + f8]), 1.0f);
    }

    float di = g_dinv[node];
    const float4* b4 = (const float4*)bias;
    float4 ba = __ldg(&b4[f8 * 2]);
    float4 bb = __ldg(&b4[f8 * 2 + 1]);
    float h2[8];
    h2[0] = fmaxf(fmaf(di, acc[0], ba.x), 0.f);
    h2[1] = fmaxf(fmaf(di, acc[1], ba.y), 0.f);
    h2[2] = fmaxf(fmaf(di, acc[2], ba.z), 0.f);
    h2[3] = fmaxf(fmaf(di, acc[3], ba.w), 0.f);
    h2[4] = fmaxf(fmaf(di, acc[4], bb.x), 0.f);
    h2[5] = fmaxf(fmaf(di, acc[5], bb.y), 0.f);
    h2[6] = fmaxf(fmaf(di, acc[6], bb.z), 0.f);
    h2[7] = fmaxf(fmaf(di, acc[7], bb.w), 0.f);

    const float4* wl4 = (const float4*)wl;
    float4 wa0 = __ldg(&wl4[f8 * 2]);
    float4 wa1 = __ldg(&wl4[f8 * 2 + 1]);
    float4 wb0 = __ldg(&wl4[16 + f8 * 2]);
    float4 wb1 = __ldg(&wl4[16 + f8 * 2 + 1]);
    float pa = h2[0] * wa0.x + h2[1] * wa0.y + h2[2] * wa0.z + h2[3] * wa0.w
             + h2[4] * wa1.x + h2[5] * wa1.y + h2[6] * wa1.z + h2[7] * wa1.w;
    float pb = h2[0] * wb0.x + h2[1] * wb0.y + h2[2] * wb0.z + h2[3] * wb0.w
             + h2[4] * wb1.x + h2[5] * wb1.y + h2[6] * wb1.z + h2[7] * wb1.w;
    #pragma unroll
    for (int o = 4; o; o >>= 1) {
        pa += __shfl_xor_sync(0xffffffffu, pa, o);
        pb += __shfl_xor_sync(0xffffffffu, pb, o);
    }
    if (f8 == 0) { g_na[node] = pa; g_nb[node] = pb; }
}

// ---------------------------------------------------------------------------
// out[e] = sigmoid(na[row] + nb[col] + b_lin)
// ---------------------------------------------------------------------------
__global__ void __launch_bounds__(256) edge_out(const int* __restrict__ row,
                                                const int* __restrict__ col,
                                                const float* __restrict__ blin,
                                                float* __restrict__ out) {
    int e = blockIdx.x * blockDim.x + threadIdx.x;
    if (e >= N_EDGES) return;
    float l = g_na[clampi(row[e])] + g_nb[clampi(col[e])] + blin[0];
    out[e] = 1.0f / (1.0f + __expf(-l));
}

// ---------------------------------------------------------------------------
extern "C" void kernel_launch(void* const* d_in, const int* in_sizes, int n_in,
                              void* d_out, int out_size) {
    const float* x    = (const float*)d_in[0];
    const int*   ei   = (const int*)d_in[1];     // int32 on device
    const float* w1   = (const float*)d_in[2];
    const float* b1   = (const float*)d_in[3];
    const float* w2   = (const float*)d_in[4];
    const float* b2   = (const float*)d_in[5];
    const float* wlin = (const float*)d_in[6];
    const float* blin = (const float*)d_in[7];
    float*       out  = (float*)d_out;

    const int* row = ei;
    const int* col = ei + N_EDGES;

    __half* xwh; cudaGetSymbolAddress((void**)&xwh, g_xwh);
    __half* hh;  cudaGetSymbolAddress((void**)&hh,  g_hh);
    int*    cnt; cudaGetSymbolAddress((void**)&cnt, g_count);

    // lazily created side stream + events (handles only; no device memory)
    static cudaStream_t s1 = nullptr;
    static cudaEvent_t ev_fork = nullptr, ev_g1 = nullptr;
    if (!s1) {
        cudaStreamCreateWithFlags(&s1, cudaStreamNonBlocking);
        cudaEventCreateWithFlags(&ev_fork, cudaEventDisableTiming);
        cudaEventCreateWithFlags(&ev_g1, cudaEventDisableTiming);
    }

    const int TB = 256;
    int grid_edges = (N_EDGES + TB - 1) / TB;
    int grid_nodes = (N_NODES + TB - 1) / TB;
    int grid_gemm1 = (N_NODES + 63) / 64;
    int grid_gemm2 = (N_NODES + 127) / 128;
    int grid_aggr  = (N_NODES + 31) / 32;

    // fork: GEMM1 (independent of bucket build) on side stream
    cudaEventRecord(ev_fork, 0);
    cudaStreamWaitEvent(s1, ev_fork, 0);
    gemm64_f32<<<grid_gemm1, TB, 0, s1>>>(x, w1, xwh, N_NODES);
    cudaEventRecord(ev_g1, s1);

    // bucket build on main stream (concurrent with GEMM1)
    cudaMemsetAsync(cnt, 0, N_NODES * sizeof(int));
    fill_buckets<<<grid_edges, TB>>>(row, col);
    make_dinv<<<grid_nodes, TB>>>();

    // join, then layer 1 aggregate
    cudaStreamWaitEvent(0, ev_g1, 0);
    aggregate1<<<grid_aggr, TB>>>(b1);

    // layer 2: tensor-core GEMM (dinv folded), then aggregate w/ fused head
    gemm64_wmma<<<grid_gemm2, TB>>>(hh, w2, xwh, N_NODES);
    aggregate2<<<grid_aggr, TB>>>(b2, wlin);

    // edge head
    edge_out<<<grid_edges, TB>>>(row, col, blin, out);
}

// round 14
// speedup vs baseline: 1.1048x; 1.1048x over previous
#include <cuda_runtime.h>
#include <cuda_fp16.h>
#include <math.h>

#define N_NODES 100000
#define N_EDGES 1000000
#define D 64
#define CAP 64                       // bucket capacity; P(Poisson(10) > 64) ~ 1e-30

// Scratch (allocation-free contract: __device__ globals)
__device__ __half g_xwh[N_NODES * D];   // GEMM output, fp16 (both layers)
__device__ __half g_hh[N_NODES * D];    // h1, fp16 (GEMM2 input)
__device__ float  g_dinv[N_NODES];      // (deg+1)^-1/2
__device__ int    g_count[N_NODES];     // in-degree (atomic fill counters)
__device__ int    g_slot[N_NODES * CAP];// bucket: src nodes per dst
__device__ float  g_na[N_NODES];        // h2 . w_lin[0:64]
__device__ float  g_nb[N_NODES];        // h2 . w_lin[64:128]

__device__ __forceinline__ int clampi(int v) {
    return v < 0 ? 0 : (v >= N_NODES ? N_NODES - 1 : v);
}

__device__ __forceinline__ unsigned long long pack2(float a, float b) {
    unsigned long long r;
    asm("mov.b64 %0, {%1, %2};" : "=l"(r) : "f"(a), "f"(b));
    return r;
}
__device__ __forceinline__ void unpack2(unsigned long long v, float& a, float& b) {
    asm("mov.b64 {%0, %1}, %2;" : "=f"(a), "=f"(b) : "l"(v));
}
__device__ __forceinline__ void ffma2(unsigned long long& d, unsigned long long a,
                                      unsigned long long b) {
    asm("fma.rn.f32x2 %0, %1, %2, %0;" : "+l"(d) : "l"(a), "l"(b));
}

// accumulate 8 halves (one uint4) scaled by s into acc[8]
__device__ __forceinline__ void acc_halves(float* acc, uint4 v, float s) {
    __half2 h0 = *reinterpret_cast<__half2*>(&v.x);
    __half2 h1 = *reinterpret_cast<__half2*>(&v.y);
    __half2 h2 = *reinterpret_cast<__half2*>(&v.z);
    __half2 h3 = *reinterpret_cast<__half2*>(&v.w);
    float2 f0 = __half22float2(h0);
    float2 f1 = __half22float2(h1);
    float2 f2 = __half22float2(h2);
    float2 f3 = __half22float2(h3);
    acc[0] = fmaf(f0.x, s, acc[0]); acc[1] = fmaf(f0.y, s, acc[1]);
    acc[2] = fmaf(f1.x, s, acc[2]); acc[3] = fmaf(f1.y, s, acc[3]);
    acc[4] = fmaf(f2.x, s, acc[4]); acc[5] = fmaf(f2.y, s, acc[5]);
    acc[6] = fmaf(f3.x, s, acc[6]); acc[7] = fmaf(f3.y, s, acc[7]);
}

// typed 4-float row loader for the GEMM (fp32 or fp16 input)
template <typename T> struct Row;
template <> struct Row<float> {
    static __device__ __forceinline__ float4 ld(const float* p, int kk) {
        return __ldg(&((const float4*)p)[kk]);
    }
};
template <> struct Row<__half> {
    static __device__ __forceinline__ float4 ld(const __half* p, int kk) {
        uint2 u = __ldg(&((const uint2*)p)[kk]);
        float2 fa = __half22float2(*reinterpret_cast<__half2*>(&u.x));
        float2 fb = __half22float2(*reinterpret_cast<__half2*>(&u.y));
        return make_float4(fa.x, fa.y, fb.x, fb.y);
    }
};

// ---------------------------------------------------------------------------
// single-pass bucket fill: slot[c*CAP + pos] = r
// ---------------------------------------------------------------------------
__global__ void __launch_bounds__(256) fill_buckets(const int* __restrict__ row,
                                                    const int* __restrict__ col) {
    int e = blockIdx.x * blockDim.x + threadIdx.x;
    if (e >= N_EDGES) return;
    int r = clampi(row[e]);
    int c = clampi(col[e]);
    int pos = atomicAdd(&g_count[c], 1);
    if (pos < CAP) g_slot[c * CAP + pos] = r;
}

// 4 nodes per thread
__global__ void __launch_bounds__(256) make_dinv() {
    int i = blockIdx.x * blockDim.x + threadIdx.x;   // over N/4 int4s
    if (i * 4 >= N_NODES) return;
    int4 c = ((const int4*)g_count)[i];
    float4 d;
    d.x = rsqrtf((float)(c.x + 1));
    d.y = rsqrtf((float)(c.y + 1));
    d.z = rsqrtf((float)(c.z + 1));
    d.w = rsqrtf((float)(c.w + 1));
    ((float4*)g_dinv)[i] = d;
}

// ---------------------------------------------------------------------------
// GEMM (packed f32x2 FMA), fp16 output, templated input type:
//   C[n,:] = (A[n,:] @ W) * (FOLD ? dinv[n] : 1)
// ---------------------------------------------------------------------------
template <bool FOLD, typename T>
__global__ void __launch_bounds__(256) gemm64(const T* __restrict__ A,
                                              const float* __restrict__ W,
                                              __half* __restrict__ C, int n) {
    __shared__ ulonglong2 ws[1024];  // W as [64][16] float4 -> packed pairs
    const float4* W4 = (const float4*)W;
    for (int i = threadIdx.x; i < 1024; i += 256) {
        float4 w = W4[i];
        ulonglong2 u;
        u.x = pack2(w.x, w.y);
        u.y = pack2(w.z, w.w);
        ws[i] = u;
    }
    __syncthreads();

    int g  = threadIdx.x >> 4;   // row group 0..15
    int j4 = threadIdx.x & 15;   // output col group (4 cols)
    int r0 = blockIdx.x * 64 + g * 4;

    ulonglong2 acc[4];
    #pragma unroll
    for (int i = 0; i < 4; i++) { acc[i].x = 0ull; acc[i].y = 0ull; }

    const T* a[4];
    bool valid[4];
    #pragma unroll
    for (int i = 0; i < 4; i++) {
        int r = r0 + i;
        valid[i] = (r < n);
        a[i] = A + (size_t)(valid[i] ? r : 0) * D;
    }

    #pragma unroll 4
    for (int kk = 0; kk < 16; kk++) {
        float4 xv[4];
        #pragma unroll
        for (int i = 0; i < 4; i++) xv[i] = Row<T>::ld(a[i], kk);
        #pragma unroll
        for (int s = 0; s < 4; s++) {
            ulonglong2 w = ws[(kk * 4 + s) * 16 + j4];
            #pragma unroll
            for (int i = 0; i < 4; i++) {
                float xs = (s == 0) ? xv[i].x : (s == 1) ? xv[i].y
                         : (s == 2) ? xv[i].z : xv[i].w;
                unsigned long long xs2 = pack2(xs, xs);
                ffma2(acc[i].x, xs2, w.x);
                ffma2(acc[i].y, xs2, w.y);
            }
        }
    }

    #pragma unroll
    for (int i = 0; i < 4; i++) {
        if (valid[i]) {
            float4 o;
            unpack2(acc[i].x, o.x, o.y);
            unpack2(acc[i].y, o.z, o.w);
            if (FOLD) {
                float sc = g_dinv[r0 + i];
                o.x *= sc; o.y *= sc; o.z *= sc; o.w *= sc;
            }
            __half2 p0 = __floats2half2_rn(o.x, o.y);
            __half2 p1 = __floats2half2_rn(o.z, o.w);
            uint2 st;
            st.x = *reinterpret_cast<unsigned*>(&p0);
            st.y = *reinterpret_cast<unsigned*>(&p1);
            ((uint2*)(C + (size_t)(r0 + i) * D))[j4] = st;
        }
    }
}

// ---------------------------------------------------------------------------
// layer-1 aggregate (GEMM1 NOT folded; apply dinv[src] here), fp16 in/out:
//   h[n] = relu(dinv[n]*(xw[n]*dinv[n] + sum xw[src]*dinv[src]) + b)
// 8 threads per node (one uint4 = 8 halves each), unrolled x4.
// ---------------------------------------------------------------------------
__global__ void __launch_bounds__(256) aggregate1(const float* __restrict__ bias) {
    int node = blockIdx.x * 32 + (threadIdx.x >> 3);
    int f8 = threadIdx.x & 7;    // uint4 index within 128B row
    if (node >= N_NODES) return;
    const uint4* xw8 = (const uint4*)g_xwh;   // row stride = 8 uint4

    float di = g_dinv[node];
    float acc[8] = {0, 0, 0, 0, 0, 0, 0, 0};
    acc_halves(acc, __ldg(&xw8[(size_t)node * 8 + f8]), di);

    const int* slots = g_slot + (size_t)node * CAP;
    int cnt = g_count[node];
    if (cnt > CAP) cnt = CAP;
    int i = 0;
    for (; i + 3 < cnt; i += 4) {
        int s0 = __ldg(&slots[i]);
        int s1 = __ldg(&slots[i + 1]);
        int s2 = __ldg(&slots[i + 2]);
        int s3 = __ldg(&slots[i + 3]);
        float d0 = __ldg(&g_dinv[s0]);
        float d1 = __ldg(&g_dinv[s1]);
        float d2 = __ldg(&g_dinv[s2]);
        float d3 = __ldg(&g_dinv[s3]);
        uint4 v0 = __ldg(&xw8[(size_t)s0 * 8 + f8]);
        uint4 v1 = __ldg(&xw8[(size_t)s1 * 8 + f8]);
        uint4 v2 = __ldg(&xw8[(size_t)s2 * 8 + f8]);
        uint4 v3 = __ldg(&xw8[(size_t)s3 * 8 + f8]);
        acc_halves(acc, v0, d0);
        acc_halves(acc, v1, d1);
        acc_halves(acc, v2, d2);
        acc_halves(acc, v3, d3);
    }
    for (; i < cnt; i++) {
        int s0 = __ldg(&slots[i]);
        float d0 = __ldg(&g_dinv[s0]);
        acc_halves(acc, __ldg(&xw8[(size_t)s0 * 8 + f8]), d0);
    }

    const float4* b4 = (const float4*)bias;
    float4 ba = __ldg(&b4[f8 * 2]);
    float4 bb = __ldg(&b4[f8 * 2 + 1]);
    float o[8];
    o[0] = fmaxf(fmaf(di, acc[0], ba.x), 0.f);
    o[1] = fmaxf(fmaf(di, acc[1], ba.y), 0.f);
    o[2] = fmaxf(fmaf(di, acc[2], ba.z), 0.f);
    o[3] = fmaxf(fmaf(di, acc[3], ba.w), 0.f);
    o[4] = fmaxf(fmaf(di, acc[4], bb.x), 0.f);
    o[5] = fmaxf(fmaf(di, acc[5], bb.y), 0.f);
    o[6] = fmaxf(fmaf(di, acc[6], bb.z), 0.f);
    o[7] = fmaxf(fmaf(di, acc[7], bb.w), 0.f);
    __half2 p0 = __floats2half2_rn(o[0], o[1]);
    __half2 p1 = __floats2half2_rn(o[2], o[3]);
    __half2 p2 = __floats2half2_rn(o[4], o[5]);
    __half2 p3 = __floats2half2_rn(o[6], o[7]);
    uint4 st;
    st.x = *reinterpret_cast<unsigned*>(&p0);
    st.y = *reinterpret_cast<unsigned*>(&p1);
    st.z = *reinterpret_cast<unsigned*>(&p2);
    st.w = *reinterpret_cast<unsigned*>(&p3);
    ((uint4*)g_hh)[(size_t)node * 8 + f8] = st;
}

// ---------------------------------------------------------------------------
// layer-2 aggregate (GEMM2 folded -> pure sum), fp16 gathers, fused edge head
// ---------------------------------------------------------------------------
__global__ void __launch_bounds__(256) aggregate2(const float* __restrict__ bias,
                                                  const float* __restrict__ wl) {
    int node = blockIdx.x * 32 + (threadIdx.x >> 3);
    int f8 = threadIdx.x & 7;
    if (node >= N_NODES) return;
    const uint4* xw8 = (const uint4*)g_xwh;

    float acc[8] = {0, 0, 0, 0, 0, 0, 0, 0};
    acc_halves(acc, __ldg(&xw8[(size_t)node * 8 + f8]), 1.0f);

    const int* slots = g_slot + (size_t)node * CAP;
    int cnt = g_count[node];
    if (cnt > CAP) cnt = CAP;
    int i = 0;
    for (; i + 3 < cnt; i += 4) {
        int s0 = __ldg(&slots[i]);
        int s1 = __ldg(&slots[i + 1]);
        int s2 = __ldg(&slots[i + 2]);
        int s3 = __ldg(&slots[i + 3]);
        uint4 v0 = __ldg(&xw8[(size_t)s0 * 8 + f8]);
        uint4 v1 = __ldg(&xw8[(size_t)s1 * 8 + f8]);
        uint4 v2 = __ldg(&xw8[(size_t)s2 * 8 + f8]);
        uint4 v3 = __ldg(&xw8[(size_t)s3 * 8 + f8]);
        acc_halves(acc, v0, 1.0f);
        acc_halves(acc, v1, 1.0f);
        acc_halves(acc, v2, 1.0f);
        acc_halves(acc, v3, 1.0f);
    }
    for (; i < cnt; i++) {
        int s0 = __ldg(&slots[i]);
        acc_halves(acc, __ldg(&xw8[(size_t)s0 * 8 + f8]), 1.0f);
    }

    float di = g_dinv[node];
    const float4* b4 = (const float4*)bias;
    float4 ba = __ldg(&b4[f8 * 2]);
    float4 bb = __ldg(&b4[f8 * 2 + 1]);
    float h2[8];
    h2[0] = fmaxf(fmaf(di, acc[0], ba.x), 0.f);
    h2[1] = fmaxf(fmaf(di, acc[1], ba.y), 0.f);
    h2[2] = fmaxf(fmaf(di, acc[2], ba.z), 0.f);
    h2[3] = fmaxf(fmaf(di, acc[3], ba.w), 0.f);
    h2[4] = fmaxf(fmaf(di, acc[4], bb.x), 0.f);
    h2[5] = fmaxf(fmaf(di, acc[5], bb.y), 0.f);
    h2[6] = fmaxf(fmaf(di, acc[6], bb.z), 0.f);
    h2[7] = fmaxf(fmaf(di, acc[7], bb.w), 0.f);

    const float4* wl4 = (const float4*)wl;
    float4 wa0 = __ldg(&wl4[f8 * 2]);
    float4 wa1 = __ldg(&wl4[f8 * 2 + 1]);
    float4 wb0 = __ldg(&wl4[16 + f8 * 2]);
    float4 wb1 = __ldg(&wl4[16 + f8 * 2 + 1]);
    float pa = h2[0] * wa0.x + h2[1] * wa0.y + h2[2] * wa0.z + h2[3] * wa0.w
             + h2[4] * wa1.x + h2[5] * wa1.y + h2[6] * wa1.z + h2[7] * wa1.w;
    float pb = h2[0] * wb0.x + h2[1] * wb0.y + h2[2] * wb0.z + h2[3] * wb0.w
             + h2[4] * wb1.x + h2[5] * wb1.y + h2[6] * wb1.z + h2[7] * wb1.w;
    #pragma unroll
    for (int o = 4; o; o >>= 1) {
        pa += __shfl_xor_sync(0xffffffffu, pa, o);
        pb += __shfl_xor_sync(0xffffffffu, pb, o);
    }
    if (f8 == 0) { g_na[node] = pa; g_nb[node] = pb; }
}

// ---------------------------------------------------------------------------
// out[e] = sigmoid(na[row] + nb[col] + b_lin); 4 edges per thread
// ---------------------------------------------------------------------------
__global__ void __launch_bounds__(256) edge_out(const int* __restrict__ row,
                                                const int* __restrict__ col,
                                                const float* __restrict__ blin,
                                                float* __restrict__ out) {
    int t = blockIdx.x * blockDim.x + threadIdx.x;   // over N_EDGES/4
    if (t * 4 >= N_EDGES) return;
    int4 r4 = ((const int4*)row)[t];
    int4 c4 = ((const int4*)col)[t];
    float bl = blin[0];
    float4 o;
    float l0 = __ldg(&g_na[clampi(r4.x)]) + __ldg(&g_nb[clampi(c4.x)]) + bl;
    float l1 = __ldg(&g_na[clampi(r4.y)]) + __ldg(&g_nb[clampi(c4.y)]) + bl;
    float l2 = __ldg(&g_na[clampi(r4.z)]) + __ldg(&g_nb[clampi(c4.z)]) + bl;
    float l3 = __ldg(&g_na[clampi(r4.w)]) + __ldg(&g_nb[clampi(c4.w)]) + bl;
    o.x = 1.0f / (1.0f + __expf(-l0));
    o.y = 1.0f / (1.0f + __expf(-l1));
    o.z = 1.0f / (1.0f + __expf(-l2));
    o.w = 1.0f / (1.0f + __expf(-l3));
    ((float4*)out)[t] = o;
}

// ---------------------------------------------------------------------------
extern "C" void kernel_launch(void* const* d_in, const int* in_sizes, int n_in,
                              void* d_out, int out_size) {
    const float* x    = (const float*)d_in[0];
    const int*   ei   = (const int*)d_in[1];     // int32 on device
    const float* w1   = (const float*)d_in[2];
    const float* b1   = (const float*)d_in[3];
    const float* w2   = (const float*)d_in[4];
    const float* b2   = (const float*)d_in[5];
    const float* wlin = (const float*)d_in[6];
    const float* blin = (const float*)d_in[7];
    float*       out  = (float*)d_out;

    const int* row = ei;
    const int* col = ei + N_EDGES;

    __half* xwh; cudaGetSymbolAddress((void**)&xwh, g_xwh);
    __half* hh;  cudaGetSymbolAddress((void**)&hh,  g_hh);
    int*    cnt; cudaGetSymbolAddress((void**)&cnt, g_count);

    // lazily created side stream + events (handles only; no device memory)
    static cudaStream_t s1 = nullptr;
    static cudaEvent_t ev_fork = nullptr, ev_g1 = nullptr;
    if (!s1) {
        cudaStreamCreateWithFlags(&s1, cudaStreamNonBlocking);
        cudaEventCreateWithFlags(&ev_fork, cudaEventDisableTiming);
        cudaEventCreateWithFlags(&ev_g1, cudaEventDisableTiming);
    }

    const int TB = 256;
    int grid_edges  = (N_EDGES + TB - 1) / TB;
    int grid_edges4 = (N_EDGES / 4 + TB - 1) / TB;
    int grid_nodes4 = (N_NODES / 4 + TB) / TB;
    int grid_gemm   = (N_NODES + 63) / 64;
    int grid_aggr   = (N_NODES + 31) / 32;

    // fork: GEMM1 (independent of bucket build) on side stream
    cudaEventRecord(ev_fork, 0);
    cudaStreamWaitEvent(s1, ev_fork, 0);
    gemm64<false, float><<<grid_gemm, TB, 0, s1>>>(x, w1, xwh, N_NODES);
    cudaEventRecord(ev_g1, s1);

    // bucket build on main stream (concurrent with GEMM1)
    cudaMemsetAsync(cnt, 0, N_NODES * sizeof(int));
    fill_buckets<<<grid_edges, TB>>>(row, col);
    make_dinv<<<grid_nodes4, TB>>>();

    // join, then layer 1 aggregate
    cudaStreamWaitEvent(0, ev_g1, 0);
    aggregate1<<<grid_aggr, TB>>>(b1);

    // layer 2 (dinv folded into GEMM; head fused into aggregate)
    gemm64<true, __half><<<grid_gemm, TB>>>(hh, w2, xwh, N_NODES);
    aggregate2<<<grid_aggr, TB>>>(b2, wlin);

    // edge head
    edge_out<<<grid_edges4, TB>>>(row, col, blin, out);
}

// round 15
// speedup vs baseline: 1.1417x; 1.0334x over previous
#include <cuda_runtime.h>
#include <cuda_fp16.h>
#include <math.h>

#define N_NODES 100000
#define N_EDGES 1000000
#define D 64
#define CAP 64                       // bucket capacity; P(Poisson(10) > 64) ~ 1e-30

// Scratch (allocation-free contract: __device__ globals)
__device__ __half g_xwh[N_NODES * D];   // GEMM output, fp16 (both layers)
__device__ __half g_hh[N_NODES * D];    // h1, fp16 (GEMM2 input)
__device__ float  g_dinv[N_NODES];      // (deg+1)^-1/2
__device__ int    g_count[N_NODES];     // in-degree; zeroed by aggregate2 each run
__device__ int    g_slot[N_NODES * CAP];// bucket: src nodes per dst
__device__ float  g_na[N_NODES];        // h2 . w_lin[0:64]
__device__ float  g_nb[N_NODES];        // h2 . w_lin[64:128]

__device__ __forceinline__ int clampi(int v) {
    return v < 0 ? 0 : (v >= N_NODES ? N_NODES - 1 : v);
}

__device__ __forceinline__ unsigned long long pack2(float a, float b) {
    unsigned long long r;
    asm("mov.b64 %0, {%1, %2};" : "=l"(r) : "f"(a), "f"(b));
    return r;
}
__device__ __forceinline__ void unpack2(unsigned long long v, float& a, float& b) {
    asm("mov.b64 {%0, %1}, %2;" : "=f"(a), "=f"(b) : "l"(v));
}
__device__ __forceinline__ void ffma2(unsigned long long& d, unsigned long long a,
                                      unsigned long long b) {
    asm("fma.rn.f32x2 %0, %1, %2, %0;" : "+l"(d) : "l"(a), "l"(b));
}

// accumulate 8 halves (one uint4) scaled by s into acc[8]
__device__ __forceinline__ void acc_halves(float* acc, uint4 v, float s) {
    __half2 h0 = *reinterpret_cast<__half2*>(&v.x);
    __half2 h1 = *reinterpret_cast<__half2*>(&v.y);
    __half2 h2 = *reinterpret_cast<__half2*>(&v.z);
    __half2 h3 = *reinterpret_cast<__half2*>(&v.w);
    float2 f0 = __half22float2(h0);
    float2 f1 = __half22float2(h1);
    float2 f2 = __half22float2(h2);
    float2 f3 = __half22float2(h3);
    acc[0] = fmaf(f0.x, s, acc[0]); acc[1] = fmaf(f0.y, s, acc[1]);
    acc[2] = fmaf(f1.x, s, acc[2]); acc[3] = fmaf(f1.y, s, acc[3]);
    acc[4] = fmaf(f2.x, s, acc[4]); acc[5] = fmaf(f2.y, s, acc[5]);
    acc[6] = fmaf(f3.x, s, acc[6]); acc[7] = fmaf(f3.y, s, acc[7]);
}

// typed 4-float row loader for the GEMM (fp32 or fp16 input)
template <typename T> struct Row;
template <> struct Row<float> {
    static __device__ __forceinline__ float4 ld(const float* p, int kk) {
        return __ldg(&((const float4*)p)[kk]);
    }
};
template <> struct Row<__half> {
    static __device__ __forceinline__ float4 ld(const __half* p, int kk) {
        uint2 u = __ldg(&((const uint2*)p)[kk]);
        float2 fa = __half22float2(*reinterpret_cast<__half2*>(&u.x));
        float2 fb = __half22float2(*reinterpret_cast<__half2*>(&u.y));
        return make_float4(fa.x, fa.y, fb.x, fb.y);
    }
};

// ---------------------------------------------------------------------------
// single-pass bucket fill: slot[c*CAP + pos] = r  (counts arrive zeroed —
// globals zero-init on load; aggregate2 re-zeroes them at the end of each run)
// ---------------------------------------------------------------------------
__global__ void __launch_bounds__(256) fill_buckets(const int* __restrict__ row,
                                                    const int* __restrict__ col) {
    int e = blockIdx.x * blockDim.x + threadIdx.x;
    if (e >= N_EDGES) return;
    int r = clampi(row[e]);
    int c = clampi(col[e]);
    int pos = atomicAdd(&g_count[c], 1);
    if (pos < CAP) g_slot[c * CAP + pos] = r;
}

// 4 nodes per thread
__global__ void __launch_bounds__(256) make_dinv() {
    cudaGridDependencySynchronize();
    int i = blockIdx.x * blockDim.x + threadIdx.x;   // over N/4 int4s
    if (i * 4 >= N_NODES) return;
    int4 c = ((const int4*)g_count)[i];
    float4 d;
    d.x = rsqrtf((float)(c.x + 1));
    d.y = rsqrtf((float)(c.y + 1));
    d.z = rsqrtf((float)(c.z + 1));
    d.w = rsqrtf((float)(c.w + 1));
    ((float4*)g_dinv)[i] = d;
}

// ---------------------------------------------------------------------------
// GEMM (packed f32x2 FMA), fp16 output, templated input type:
//   C[n,:] = (A[n,:] @ W) * (FOLD ? dinv[n] : 1)
// ---------------------------------------------------------------------------
template <bool FOLD, typename T>
__global__ void __launch_bounds__(256) gemm64(const T* __restrict__ A,
                                              const float* __restrict__ W,
                                              __half* __restrict__ C, int n) {
    cudaGridDependencySynchronize();
    __shared__ ulonglong2 ws[1024];  // W as [64][16] float4 -> packed pairs
    const float4* W4 = (const float4*)W;
    for (int i = threadIdx.x; i < 1024; i += 256) {
        float4 w = W4[i];
        ulonglong2 u;
        u.x = pack2(w.x, w.y);
        u.y = pack2(w.z, w.w);
        ws[i] = u;
    }
    __syncthreads();

    int g  = threadIdx.x >> 4;   // row group 0..15
    int j4 = threadIdx.x & 15;   // output col group (4 cols)
    int r0 = blockIdx.x * 64 + g * 4;

    ulonglong2 acc[4];
    #pragma unroll
    for (int i = 0; i < 4; i++) { acc[i].x = 0ull; acc[i].y = 0ull; }

    const T* a[4];
    bool valid[4];
    #pragma unroll
    for (int i = 0; i < 4; i++) {
        int r = r0 + i;
        valid[i] = (r < n);
        a[i] = A + (size_t)(valid[i] ? r : 0) * D;
    }

    #pragma unroll 4
    for (int kk = 0; kk < 16; kk++) {
        float4 xv[4];
        #pragma unroll
        for (int i = 0; i < 4; i++) xv[i] = Row<T>::ld(a[i], kk);
        #pragma unroll
        for (int s = 0; s < 4; s++) {
            ulonglong2 w = ws[(kk * 4 + s) * 16 + j4];
            #pragma unroll
            for (int i = 0; i < 4; i++) {
                float xs = (s == 0) ? xv[i].x : (s == 1) ? xv[i].y
                         : (s == 2) ? xv[i].z : xv[i].w;
                unsigned long long xs2 = pack2(xs, xs);
                ffma2(acc[i].x, xs2, w.x);
                ffma2(acc[i].y, xs2, w.y);
            }
        }
    }

    #pragma unroll
    for (int i = 0; i < 4; i++) {
        if (valid[i]) {
            float4 o;
            unpack2(acc[i].x, o.x, o.y);
            unpack2(acc[i].y, o.z, o.w);
            if (FOLD) {
                float sc = g_dinv[r0 + i];
                o.x *= sc; o.y *= sc; o.z *= sc; o.w *= sc;
            }
            __half2 p0 = __floats2half2_rn(o.x, o.y);
            __half2 p1 = __floats2half2_rn(o.z, o.w);
            uint2 st;
            st.x = *reinterpret_cast<unsigned*>(&p0);
            st.y = *reinterpret_cast<unsigned*>(&p1);
            ((uint2*)(C + (size_t)(r0 + i) * D))[j4] = st;
        }
    }
}

// ---------------------------------------------------------------------------
// layer-1 aggregate (GEMM1 NOT folded; apply dinv[src] here), fp16 in/out:
//   h[n] = relu(dinv[n]*(xw[n]*dinv[n] + sum xw[src]*dinv[src]) + b)
// 8 threads per node (one uint4 = 8 halves each), unrolled x4.
// ---------------------------------------------------------------------------
__global__ void __launch_bounds__(256) aggregate1(const float* __restrict__ bias) {
    cudaGridDependencySynchronize();
    int node = blockIdx.x * 32 + (threadIdx.x >> 3);
    int f8 = threadIdx.x & 7;    // uint4 index within 128B row
    if (node >= N_NODES) return;
    const uint4* xw8 = (const uint4*)g_xwh;   // row stride = 8 uint4

    float di = g_dinv[node];
    float acc[8] = {0, 0, 0, 0, 0, 0, 0, 0};
    acc_halves(acc, __ldg(&xw8[(size_t)node * 8 + f8]), di);

    const int* slots = g_slot + (size_t)node * CAP;
    int cnt = g_count[node];
    if (cnt > CAP) cnt = CAP;
    int i = 0;
    for (; i + 3 < cnt; i += 4) {
        int s0 = __ldg(&slots[i]);
        int s1 = __ldg(&slots[i + 1]);
        int s2 = __ldg(&slots[i + 2]);
        int s3 = __ldg(&slots[i + 3]);
        float d0 = __ldg(&g_dinv[s0]);
        float d1 = __ldg(&g_dinv[s1]);
        float d2 = __ldg(&g_dinv[s2]);
        float d3 = __ldg(&g_dinv[s3]);
        uint4 v0 = __ldg(&xw8[(size_t)s0 * 8 + f8]);
        uint4 v1 = __ldg(&xw8[(size_t)s1 * 8 + f8]);
        uint4 v2 = __ldg(&xw8[(size_t)s2 * 8 + f8]);
        uint4 v3 = __ldg(&xw8[(size_t)s3 * 8 + f8]);
        acc_halves(acc, v0, d0);
        acc_halves(acc, v1, d1);
        acc_halves(acc, v2, d2);
        acc_halves(acc, v3, d3);
    }
    for (; i < cnt; i++) {
        int s0 = __ldg(&slots[i]);
        float d0 = __ldg(&g_dinv[s0]);
        acc_halves(acc, __ldg(&xw8[(size_t)s0 * 8 + f8]), d0);
    }

    const float4* b4 = (const float4*)bias;
    float4 ba = __ldg(&b4[f8 * 2]);
    float4 bb = __ldg(&b4[f8 * 2 + 1]);
    float o[8];
    o[0] = fmaxf(fmaf(di, acc[0], ba.x), 0.f);
    o[1] = fmaxf(fmaf(di, acc[1], ba.y), 0.f);
    o[2] = fmaxf(fmaf(di, acc[2], ba.z), 0.f);
    o[3] = fmaxf(fmaf(di, acc[3], ba.w), 0.f);
    o[4] = fmaxf(fmaf(di, acc[4], bb.x), 0.f);
    o[5] = fmaxf(fmaf(di, acc[5], bb.y), 0.f);
    o[6] = fmaxf(fmaf(di, acc[6], bb.z), 0.f);
    o[7] = fmaxf(fmaf(di, acc[7], bb.w), 0.f);
    __half2 p0 = __floats2half2_rn(o[0], o[1]);
    __half2 p1 = __floats2half2_rn(o[2], o[3]);
    __half2 p2 = __floats2half2_rn(o[4], o[5]);
    __half2 p3 = __floats2half2_rn(o[6], o[7]);
    uint4 st;
    st.x = *reinterpret_cast<unsigned*>(&p0);
    st.y = *reinterpret_cast<unsigned*>(&p1);
    st.z = *reinterpret_cast<unsigned*>(&p2);
    st.w = *reinterpret_cast<unsigned*>(&p3);
    ((uint4*)g_hh)[(size_t)node * 8 + f8] = st;
}

// ---------------------------------------------------------------------------
// layer-2 aggregate (GEMM2 folded -> pure sum), fp16 gathers, fused edge head.
// Also restores the g_count=0 invariant for the next graph replay.
// ---------------------------------------------------------------------------
__global__ void __launch_bounds__(256) aggregate2(const float* __restrict__ bias,
                                                  const float* __restrict__ wl) {
    cudaGridDependencySynchronize();
    int node = blockIdx.x * 32 + (threadIdx.x >> 3);
    int f8 = threadIdx.x & 7;
    if (node >= N_NODES) return;
    const uint4* xw8 = (const uint4*)g_xwh;

    float acc[8] = {0, 0, 0, 0, 0, 0, 0, 0};
    acc_halves(acc, __ldg(&xw8[(size_t)node * 8 + f8]), 1.0f);

    const int* slots = g_slot + (size_t)node * CAP;
    int cnt = g_count[node];
    if (cnt > CAP) cnt = CAP;
    int i = 0;
    for (; i + 3 < cnt; i += 4) {
        int s0 = __ldg(&slots[i]);
        int s1 = __ldg(&slots[i + 1]);
        int s2 = __ldg(&slots[i + 2]);
        int s3 = __ldg(&slots[i + 3]);
        uint4 v0 = __ldg(&xw8[(size_t)s0 * 8 + f8]);
        uint4 v1 = __ldg(&xw8[(size_t)s1 * 8 + f8]);
        uint4 v2 = __ldg(&xw8[(size_t)s2 * 8 + f8]);
        uint4 v3 = __ldg(&xw8[(size_t)s3 * 8 + f8]);
        acc_halves(acc, v0, 1.0f);
        acc_halves(acc, v1, 1.0f);
        acc_halves(acc, v2, 1.0f);
        acc_halves(acc, v3, 1.0f);
    }
    for (; i < cnt; i++) {
        int s0 = __ldg(&slots[i]);
        acc_halves(acc, __ldg(&xw8[(size_t)s0 * 8 + f8]), 1.0f);
    }

    float di = g_dinv[node];
    const float4* b4 = (const float4*)bias;
    float4 ba = __ldg(&b4[f8 * 2]);
    float4 bb = __ldg(&b4[f8 * 2 + 1]);
    float h2[8];
    h2[0] = fmaxf(fmaf(di, acc[0], ba.x), 0.f);
    h2[1] = fmaxf(fmaf(di, acc[1], ba.y), 0.f);
    h2[2] = fmaxf(fmaf(di, acc[2], ba.z), 0.f);
    h2[3] = fmaxf(fmaf(di, acc[3], ba.w), 0.f);
    h2[4] = fmaxf(fmaf(di, acc[4], bb.x), 0.f);
    h2[5] = fmaxf(fmaf(di, acc[5], bb.y), 0.f);
    h2[6] = fmaxf(fmaf(di, acc[6], bb.z), 0.f);
    h2[7] = fmaxf(fmaf(di, acc[7], bb.w), 0.f);

    const float4* wl4 = (const float4*)wl;
    float4 wa0 = __ldg(&wl4[f8 * 2]);
    float4 wa1 = __ldg(&wl4[f8 * 2 + 1]);
    float4 wb0 = __ldg(&wl4[16 + f8 * 2]);
    float4 wb1 = __ldg(&wl4[16 + f8 * 2 + 1]);
    float pa = h2[0] * wa0.x + h2[1] * wa0.y + h2[2] * wa0.z + h2[3] * wa0.w
             + h2[4] * wa1.x + h2[5] * wa1.y + h2[6] * wa1.z + h2[7] * wa1.w;
    float pb = h2[0] * wb0.x + h2[1] * wb0.y + h2[2] * wb0.z + h2[3] * wb0.w
             + h2[4] * wb1.x + h2[5] * wb1.y + h2[6] * wb1.z + h2[7] * wb1.w;
    #pragma unroll
    for (int o = 4; o; o >>= 1) {
        pa += __shfl_xor_sync(0xffffffffu, pa, o);
        pb += __shfl_xor_sync(0xffffffffu, pb, o);
    }
    if (f8 == 0) {
        g_na[node] = pa;
        g_nb[node] = pb;
        g_count[node] = 0;   // restore invariant (replaces memset node)
    }
}

// ---------------------------------------------------------------------------
// out[e] = sigmoid(na[row] + nb[col] + b_lin); 4 edges per thread
// ---------------------------------------------------------------------------
__global__ void __launch_bounds__(256) edge_out(const int* __restrict__ row,
                                                const int* __restrict__ col,
                                                const float* __restrict__ blin,
                                                float* __restrict__ out) {
    cudaGridDependencySynchronize();
    int t = blockIdx.x * blockDim.x + threadIdx.x;   // over N_EDGES/4
    if (t * 4 >= N_EDGES) return;
    int4 r4 = ((const int4*)row)[t];
    int4 c4 = ((const int4*)col)[t];
    float bl = blin[0];
    float4 o;
    float l0 = __ldg(&g_na[clampi(r4.x)]) + __ldg(&g_nb[clampi(c4.x)]) + bl;
    float l1 = __ldg(&g_na[clampi(r4.y)]) + __ldg(&g_nb[clampi(c4.y)]) + bl;
    float l2 = __ldg(&g_na[clampi(r4.z)]) + __ldg(&g_nb[clampi(c4.z)]) + bl;
    float l3 = __ldg(&g_na[clampi(r4.w)]) + __ldg(&g_nb[clampi(c4.w)]) + bl;
    o.x = 1.0f / (1.0f + __expf(-l0));
    o.y = 1.0f / (1.0f + __expf(-l1));
    o.z = 1.0f / (1.0f + __expf(-l2));
    o.w = 1.0f / (1.0f + __expf(-l3));
    ((float4*)out)[t] = o;
}

// ---------------------------------------------------------------------------
extern "C" void kernel_launch(void* const* d_in, const int* in_sizes, int n_in,
                              void* d_out, int out_size) {
    const float* x    = (const float*)d_in[0];
    const int*   ei   = (const int*)d_in[1];     // int32 on device
    const float* w1   = (const float*)d_in[2];
    const float* b1   = (const float*)d_in[3];
    const float* w2   = (const float*)d_in[4];
    const float* b2   = (const float*)d_in[5];
    const float* wlin = (const float*)d_in[6];
    const float* blin = (const float*)d_in[7];
    float*       out  = (float*)d_out;

    const int* row = ei;
    const int* col = ei + N_EDGES;

    __half* xwh; cudaGetSymbolAddress((void**)&xwh, g_xwh);
    __half* hh;  cudaGetSymbolAddress((void**)&hh,  g_hh);

    // lazily created side stream + events (handles only; no device memory)
    static cudaStream_t s1 = nullptr;
    static cudaEvent_t ev_fork = nullptr, ev_g1 = nullptr;
    if (!s1) {
        cudaStreamCreateWithFlags(&s1, cudaStreamNonBlocking);
        cudaEventCreateWithFlags(&ev_fork, cudaEventDisableTiming);
        cudaEventCreateWithFlags(&ev_g1, cudaEventDisableTiming);
    }

    const int TB = 256;
    int grid_edges  = (N_EDGES + TB - 1) / TB;
    int grid_edges4 = (N_EDGES / 4 + TB - 1) / TB;
    int grid_nodes4 = (N_NODES / 4 + TB) / TB;
    int grid_gemm   = (N_NODES + 63) / 64;
    int grid_aggr   = (N_NODES + 31) / 32;

    // PDL launch config helper (programmatic stream serialization)
    cudaLaunchAttribute pss_attr[1];
    pss_attr[0].id = cudaLaunchAttributeProgrammaticStreamSerialization;
    pss_attr[0].val.programmaticStreamSerializationAllowed = 1;
    auto pss_cfg = [&](int grid) {
        cudaLaunchConfig_t cfg = {};
        cfg.gridDim = dim3(grid);
        cfg.blockDim = dim3(TB);
        cfg.stream = 0;
        cfg.attrs = pss_attr;
        cfg.numAttrs = 1;
        return cfg;
    };

    // fork: GEMM1 (independent of bucket build) on side stream
    cudaEventRecord(ev_fork, 0);
    cudaStreamWaitEvent(s1, ev_fork, 0);
    gemm64<false, float><<<grid_gemm, TB, 0, s1>>>(x, w1, xwh, N_NODES);
    cudaEventRecord(ev_g1, s1);

    // bucket build on main stream (concurrent with GEMM1); counts arrive zeroed
    fill_buckets<<<grid_edges, TB>>>(row, col);
    {
        cudaLaunchConfig_t cfg = pss_cfg(grid_nodes4);
        cudaLaunchKernelEx(&cfg, make_dinv);
    }

    // join, then layer 1 aggregate (PDL over make_dinv; event edge to gemm1)
    cudaStreamWaitEvent(0, ev_g1, 0);
    {
        cudaLaunchConfig_t cfg = pss_cfg(grid_aggr);
        cudaLaunchKernelEx(&cfg, aggregate1, b1);
    }

    // layer 2 (dinv folded into GEMM; head fused into aggregate)
    {
        cudaLaunchConfig_t cfg = pss_cfg(grid_gemm);
        cudaLaunchKernelEx(&cfg, gemm64<true, __half>,
                           (const __half*)hh, w2, (__half*)xwh, (int)N_NODES);
    }
    {
        cudaLaunchConfig_t cfg = pss_cfg(grid_aggr);
        cudaLaunchKernelEx(&cfg, aggregate2, b2, wlin);
    }

    // edge head
    {
        cudaLaunchConfig_t cfg = pss_cfg(grid_edges4);
        cudaLaunchKernelEx(&cfg, edge_out, row, col, blin, out);
    }
}